// round 1
// baseline (speedup 1.0000x reference)
#include <cuda_runtime.h>
#include <cstddef>

// out[b,n] = sum_m x[b,n,m] * w1[m,0,n] + b1[n]
// x:  [B=256, N=4096, M=64] float32, m contiguous
// w1: [M=64, 1, N=4096]     float32, n contiguous (stride-N per m)
// b1: [1, N=4096, 1]        float32
// out: [B, N] float32

constexpr int B_TOT = 256;
constexpr int N_TOT = 4096;
constexpr int M_TOT = 64;

constexpr int TILE_N = 16;          // n's per block
constexpr int THREADS = 256;        // 16 groups of 16 lanes
constexpr int B_SPLIT = 8;
constexpr int B_PER_BLOCK = B_TOT / B_SPLIT;   // 32

__global__ __launch_bounds__(THREADS)
void superlinear_kernel(const float* __restrict__ x,
                        const float* __restrict__ w,
                        const float* __restrict__ bias,
                        float* __restrict__ out) {
    const int t  = threadIdx.x;
    const int g  = t >> 4;          // group id = local n, 0..15
    const int l  = t & 15;          // lane within group, 0..15
    const int n  = blockIdx.x * TILE_N + g;
    const int b0 = blockIdx.y * B_PER_BLOCK;

    // Loop-invariant weight vector for this (n, l): w[m][n], m = 4l..4l+3.
    // Strided gathers, but w is 1 MB and L2-resident after the first wave.
    const int m0 = l << 2;
    float4 wv;
    wv.x = __ldg(&w[(size_t)(m0 + 0) * N_TOT + n]);
    wv.y = __ldg(&w[(size_t)(m0 + 1) * N_TOT + n]);
    wv.z = __ldg(&w[(size_t)(m0 + 2) * N_TOT + n]);
    wv.w = __ldg(&w[(size_t)(m0 + 3) * N_TOT + n]);
    const float bv = __ldg(&bias[n]);

    // x row for (b, n): 64 floats = 16 float4; lane l takes float4 #l.
    // 16 lanes * 16B = one fully-coalesced 256B row; a warp covers 2
    // consecutive n rows = 512B contiguous.
    const float4* xp = reinterpret_cast<const float4*>(x)
                       + ((size_t)b0 * N_TOT + n) * (M_TOT / 4) + l;
    const size_t x_bstride = (size_t)N_TOT * (M_TOT / 4);  // float4 per b step

    float* op = out + (size_t)b0 * N_TOT + n;

    #pragma unroll 4
    for (int b = 0; b < B_PER_BLOCK; ++b) {
        float4 xv = xp[(size_t)b * x_bstride];
        float s = xv.x * wv.x + xv.y * wv.y + xv.z * wv.z + xv.w * wv.w;
        // reduce across the 16-lane group (xor masks stay within the group)
        s += __shfl_xor_sync(0xffffffffu, s, 8);
        s += __shfl_xor_sync(0xffffffffu, s, 4);
        s += __shfl_xor_sync(0xffffffffu, s, 2);
        s += __shfl_xor_sync(0xffffffffu, s, 1);
        if (l == 0) op[(size_t)b * N_TOT] = s + bv;
    }
}

extern "C" void kernel_launch(void* const* d_in, const int* in_sizes, int n_in,
                              void* d_out, int out_size) {
    const float* x    = (const float*)d_in[0];  // [B, N, M]
    const float* w1   = (const float*)d_in[1];  // [M, 1, N]
    const float* b1   = (const float*)d_in[2];  // [1, N, 1]
    float* out        = (float*)d_out;          // [B, N]

    dim3 grid(N_TOT / TILE_N, B_SPLIT);
    superlinear_kernel<<<grid, THREADS>>>(x, w1, b1, out);
}